// round 14
// baseline (speedup 1.0000x reference)
// R14: 512 threads / 16 warps (4 per SMSP) for LDSM-latency hiding; M=512 tile,
// A single-buffered (149.5KB) + B double-buffered; per-warp tile unchanged.
#include <cuda_runtime.h>
#include <cuda_bf16.h>
#include <cstdint>

#define DINL __device__ __forceinline__

// ---------------- device scratch (no allocations allowed) -------------------
// x channel-last bf16 hi/lo: row = flat(b,x,y,z), 144 ci per row (288B).
// +1024 pad rows: slab reads reach <=584 rows past the last start; overhang
// products land only in discarded oy>=30 / oz>=30 outputs. .bss zero-init.
__device__ __align__(16) __nv_bfloat16 g_xh[(262144 + 1024) * 144];
__device__ __align__(16) __nv_bfloat16 g_xl[(262144 + 1024) * 144];
// W rows: [(kx*3+kz)*9 + chunk*3 + ky][co32][ci64] = 2592 rows x 128B
__device__ __align__(16) __nv_bfloat16 g_bh[2592 * 64];
__device__ __align__(16) __nv_bfloat16 g_bl[2592 * 64];

// ---------------- PTX helpers ----------------------------------------------
DINL uint32_t smem_u32(const void* p) {
    uint32_t a;
    asm("{ .reg .u64 t; cvta.to.shared.u64 t, %1; cvt.u32.u64 %0, t; }" : "=r"(a) : "l"(p));
    return a;
}
DINL void cp16(uint32_t s, const void* g) {
    asm volatile("cp.async.cg.shared.global [%0], [%1], 16;" :: "r"(s), "l"(g));
}
DINL void cp_commit() { asm volatile("cp.async.commit_group;"); }
DINL void cp_wait0()  { asm volatile("cp.async.wait_group 0;" ::: "memory"); }

DINL void ldm4(uint32_t& r0, uint32_t& r1, uint32_t& r2, uint32_t& r3, uint32_t a) {
    asm volatile("ldmatrix.sync.aligned.m8n8.x4.shared.b16 {%0,%1,%2,%3}, [%4];"
                 : "=r"(r0), "=r"(r1), "=r"(r2), "=r"(r3) : "r"(a));
}
DINL void mma16816(float& d0, float& d1, float& d2, float& d3,
                   uint32_t a0, uint32_t a1, uint32_t a2, uint32_t a3,
                   uint32_t b0, uint32_t b1) {
    asm volatile(
        "mma.sync.aligned.m16n8k16.row.col.f32.bf16.bf16.f32 "
        "{%0,%1,%2,%3}, {%4,%5,%6,%7}, {%8,%9}, {%0,%1,%2,%3};"
        : "+f"(d0), "+f"(d1), "+f"(d2), "+f"(d3)
        : "r"(a0), "r"(a1), "r"(a2), "r"(a3), "r"(b0), "r"(b1));
}

// ---------------- prep 1: x -> channel-last bf16 hi/lo ----------------------
__global__ void prep_x(const float* __restrict__ x) {
    __shared__ float t[144 * 33];
    int bid = blockIdx.x;                 // 8192 = 8b*32x*32y
    int b = bid >> 10, xx = (bid >> 5) & 31, y = bid & 31;
    for (int i = threadIdx.x; i < 144 * 32; i += 128) {
        int ci = i >> 5, z = i & 31;
        t[ci * 33 + z] = x[(size_t)(b * 144 + ci) * 32768 + xx * 1024 + y * 32 + z];
    }
    __syncthreads();
    size_t rb = ((((size_t)b * 32 + xx) * 32 + y) * 32) * 72;   // uint32 units
    uint32_t* oh = (uint32_t*)g_xh;
    uint32_t* ol = (uint32_t*)g_xl;
    for (int j = threadIdx.x; j < 32 * 72; j += 128) {
        int z = j / 72, cp = j % 72, ci = cp * 2;
        float f0 = t[ci * 33 + z], f1 = t[(ci + 1) * 33 + z];
        __nv_bfloat16 h0 = __float2bfloat16(f0), h1 = __float2bfloat16(f1);
        __nv_bfloat16 l0 = __float2bfloat16(f0 - __bfloat162float(h0));
        __nv_bfloat16 l1 = __float2bfloat16(f1 - __bfloat162float(h1));
        __nv_bfloat162 vh; vh.x = h0; vh.y = h1;
        __nv_bfloat162 vl; vl.x = l0; vl.y = l1;
        oh[rb + (size_t)z * 72 + cp] = *(uint32_t*)&vh;
        ol[rb + (size_t)z * 72 + cp] = *(uint32_t*)&vl;
    }
}

// ---------------- prep 2: W -> B rows hi/lo ---------------------------------
__global__ void prep_w(const float* __restrict__ W) {
    int i = blockIdx.x * 256 + threadIdx.x;
    if (i >= 2592 * 64) return;
    int row = i >> 6, cil = i & 63;
    int co = row & 31, tt = row >> 5;
    int ky = tt % 3, chunk = (tt / 3) % 3, kxkz = tt / 9;
    int kx = kxkz / 3, kz = kxkz % 3;
    int ci = chunk * 64 + cil;
    float f = (ci < 144) ? W[(size_t)(co * 144 + ci) * 27 + kx * 9 + ky * 3 + kz] : 0.f;
    __nv_bfloat16 h = __float2bfloat16(f);
    g_bh[i] = h;
    g_bl[i] = __float2bfloat16(f - __bfloat162float(h));
}

// ---------------- main: implicit GEMM, M=512, 16 warps ----------------------
// CTA: M=512 = 16oy x 32oz, N=32. 512 thr; warp w owns M [w*32, w*32+32).
// Grid 480 = 8b * 30ox * 2oyblk.
// A unit (kx,chunk): ONE 584-row slab, single-buffered (max read row 577).
// kz & ky are row offsets at read time; A swizzle term (lane+kz)&7.
// B unit (kx,chunk,kz): 96 rows, double-buffered.
// Pipeline invariant: A(u+1) commits only after last reader of A(u) (end of
// kz==2), so wait_group 0 at each s-top waits exactly {B(s) [, A(u) if kz==0]}.
// smem: A 2x74752 = 149504 | B 2x24576 = 49152 -> 198656 (194KB), occ 1.
static constexpr int A_SLOT = 584 * 128;            // 74752 (hi or lo)
static constexpr int OFF_B  = 2 * A_SLOT;           // 149504
static constexpr int B_SLOT = 96 * 128;             // 12288
static constexpr int B_BUF  = 2 * B_SLOT;           // 24576
static constexpr int SMEM_TOT = OFF_B + 2 * B_BUF;  // 198656

DINL void stage_A(int u, int b, int ox, int oy0, int tid, uint32_t dst) {
    int kx = u / 3, chunk = u % 3;
    int cgmax = (chunk < 2) ? 8 : 2;
    int cgsh  = (chunk < 2) ? 3 : 1;
    int f0 = ((b * 32 + ox + kx) * 32 + oy0) * 32;
    const char* gh = (const char*)g_xh + (size_t)f0 * 288 + chunk * 128;
    const char* gl = (const char*)g_xl + (size_t)f0 * 288 + chunk * 128;
    for (int idx = tid; idx < 584 * cgmax; idx += 512) {
        int row = idx >> cgsh, cg = idx & (cgmax - 1);
        uint32_t d = dst + row * 128 + ((cg ^ (row & 7)) << 4);
        cp16(d,          gh + (size_t)row * 288 + cg * 16);
        cp16(d + A_SLOT, gl + (size_t)row * 288 + cg * 16);
    }
}
DINL void stage_B(int s, int tid, uint32_t dst) {
    int kx = s / 9, chunk = (s % 9) / 3, kz = s % 3;
    int cgmax = (chunk < 2) ? 8 : 2;
    int cgsh  = (chunk < 2) ? 3 : 1;
    int brow0 = ((kx * 3 + kz) * 9 + chunk * 3) * 32;
    const char* gh = (const char*)g_bh + (size_t)brow0 * 128;
    const char* gl = (const char*)g_bl + (size_t)brow0 * 128;
    for (int idx = tid; idx < 96 * cgmax; idx += 512) {
        int row = idx >> cgsh, cg = idx & (cgmax - 1);
        uint32_t d = dst + row * 128 + ((cg ^ (row & 7)) << 4);
        cp16(d,          gh + (size_t)row * 128 + cg * 16);
        cp16(d + B_SLOT, gl + (size_t)row * 128 + cg * 16);
    }
}

__global__ __launch_bounds__(512, 1)
void conv_mma(float* __restrict__ out) {
    extern __shared__ char smem[];
    uint32_t sb = smem_u32(smem);
    int tid = threadIdx.x, w = tid >> 5, lane = tid & 31;

    int bid = blockIdx.x;                       // 480 = 8b * 30ox * 2oyblk
    int b = bid / 60, r = bid % 60, ox = r / 2, oy0 = (r % 2) * 16;

    // canonical ldmatrix.x4 lane geometry (proven R11/R13)
    int lrow = (lane & 7) + (((lane >> 3) & 1) << 3);
    int lblk = lane >> 4;

    float c[2][4][4];
#pragma unroll
    for (int m = 0; m < 2; m++)
#pragma unroll
        for (int n = 0; n < 4; n++)
#pragma unroll
            for (int j = 0; j < 4; j++) c[m][n][j] = 0.f;

    stage_A(0, b, ox, oy0, tid, sb);
    cp_commit();
    stage_B(0, tid, sb + OFF_B);
    cp_commit();

    for (int s = 0; s < 27; s++) {
        int u = s / 3, kz = s % 3, chunk = u % 3;
        uint32_t bbuf = sb + OFF_B + (s & 1) * B_BUF;

        cp_wait0();                 // pending here: B(s) [+ A(u) iff kz==0]
        __syncthreads();
        if (s + 1 < 27) {
            stage_B(s + 1, tid, sb + OFF_B + ((s + 1) & 1) * B_BUF);
            cp_commit();
        }

        int ksteps = (chunk < 2) ? 4 : 1;
        uint32_t csA = (uint32_t)((lane + kz) & 7);
        uint32_t csB = (uint32_t)(lane & 7);
#pragma unroll 1
        for (int ks = 0; ks < ksteps; ks++) {
            uint32_t colA = (uint32_t)(((ks * 2 + lblk) ^ csA) << 4);
            uint32_t colB = (uint32_t)(((ks * 2 + lblk) ^ csB) << 4);
#pragma unroll
            for (int ky = 0; ky < 3; ky++) {
                uint32_t br0 = (uint32_t)(ky * 32 + lrow) * 128;
                uint32_t br1 = (uint32_t)(ky * 32 + 16 + lrow) * 128;
                uint32_t bh0, bh1, bh2, bh3, bh4, bh5, bh6, bh7;
                ldm4(bh0, bh1, bh2, bh3, bbuf + br0 + colB);
                ldm4(bh4, bh5, bh6, bh7, bbuf + br1 + colB);
                uint32_t bl0, bl1, bl2, bl3, bl4, bl5, bl6, bl7;
                ldm4(bl0, bl1, bl2, bl3, bbuf + B_SLOT + br0 + colB);
                ldm4(bl4, bl5, bl6, bl7, bbuf + B_SLOT + br1 + colB);
#pragma unroll
                for (int m = 0; m < 2; m++) {
                    uint32_t arow =
                        (uint32_t)(w * 32 + m * 16 + ky * 32 + kz + lrow) * 128;
                    uint32_t a0, a1, a2, a3, q0, q1, q2, q3;
                    ldm4(a0, a1, a2, a3, sb + arow + colA);            // xh
                    ldm4(q0, q1, q2, q3, sb + A_SLOT + arow + colA);   // xl
                    // pass hh
                    mma16816(c[m][0][0], c[m][0][1], c[m][0][2], c[m][0][3], a0, a1, a2, a3, bh0, bh2);
                    mma16816(c[m][1][0], c[m][1][1], c[m][1][2], c[m][1][3], a0, a1, a2, a3, bh1, bh3);
                    mma16816(c[m][2][0], c[m][2][1], c[m][2][2], c[m][2][3], a0, a1, a2, a3, bh4, bh6);
                    mma16816(c[m][3][0], c[m][3][1], c[m][3][2], c[m][3][3], a0, a1, a2, a3, bh5, bh7);
                    // pass hl
                    mma16816(c[m][0][0], c[m][0][1], c[m][0][2], c[m][0][3], a0, a1, a2, a3, bl0, bl2);
                    mma16816(c[m][1][0], c[m][1][1], c[m][1][2], c[m][1][3], a0, a1, a2, a3, bl1, bl3);
                    mma16816(c[m][2][0], c[m][2][1], c[m][2][2], c[m][2][3], a0, a1, a2, a3, bl4, bl6);
                    mma16816(c[m][3][0], c[m][3][1], c[m][3][2], c[m][3][3], a0, a1, a2, a3, bl5, bl7);
                    // pass lh
                    mma16816(c[m][0][0], c[m][0][1], c[m][0][2], c[m][0][3], q0, q1, q2, q3, bh0, bh2);
                    mma16816(c[m][1][0], c[m][1][1], c[m][1][2], c[m][1][3], q0, q1, q2, q3, bh1, bh3);
                    mma16816(c[m][2][0], c[m][2][1], c[m][2][2], c[m][2][3], q0, q1, q2, q3, bh4, bh6);
                    mma16816(c[m][3][0], c[m][3][1], c[m][3][2], c[m][3][3], q0, q1, q2, q3, bh5, bh7);
                }
            }
        }

        if (kz == 2 && u + 1 < 9) {
            __syncthreads();                    // all warps done reading A(u)
            stage_A(u + 1, b, ox, oy0, tid, sb);
            cp_commit();                        // waited at next s-top (kz==0)
        }
    }

    // ---- epilogue: Mrow = w*32 + m*16 + rr(+8); oy = oy0 + Mrow/32, oz = Mrow%32
    int rr = lane >> 2;
    int nb = (lane & 3) * 2;
#pragma unroll
    for (int m = 0; m < 2; m++)
#pragma unroll
        for (int half = 0; half < 2; half++) {
            int Mrow = w * 32 + m * 16 + rr + half * 8;
            int oy = oy0 + (Mrow >> 5);
            int oz = Mrow & 31;
            if (oy < 30 && oz < 30) {
                float* ob = out + (size_t)b * 32 * 27000 + ox * 900 + oy * 30 + oz;
#pragma unroll
                for (int nt = 0; nt < 4; nt++) {
                    int n = nt * 8 + nb;
                    ob[(size_t)n * 27000]       = c[m][nt][half * 2];
                    ob[(size_t)(n + 1) * 27000] = c[m][nt][half * 2 + 1];
                }
            }
        }
}

// ---------------- host ------------------------------------------------------
extern "C" void kernel_launch(void* const* d_in, const int* in_sizes, int n_in,
                              void* d_out, int out_size) {
    const float* x = (const float*)d_in[0];
    const float* W = (const float*)d_in[1];
    if (n_in >= 2 && in_sizes[0] == 124416) { const float* t = x; x = W; W = t; }
    float* out = (float*)d_out;

    cudaFuncSetAttribute(conv_mma, cudaFuncAttributeMaxDynamicSharedMemorySize, SMEM_TOT);

    prep_x<<<8192, 128>>>(x);
    prep_w<<<(2592 * 64 + 255) / 256, 256>>>(W);
    conv_mma<<<480, 512, SMEM_TOT>>>(out);
}

// round 15
// speedup vs baseline: 1.0538x; 1.0538x over previous
// R15: R13 base (M=256, 8 warps, dbl-buffered A+B) + register double-buffered
// fragment pipeline: loads for iter t+1 issue before MMAs of iter t.
#include <cuda_runtime.h>
#include <cuda_bf16.h>
#include <cstdint>

#define DINL __device__ __forceinline__

// ---------------- device scratch (no allocations allowed) -------------------
__device__ __align__(16) __nv_bfloat16 g_xh[(262144 + 1024) * 144];
__device__ __align__(16) __nv_bfloat16 g_xl[(262144 + 1024) * 144];
__device__ __align__(16) __nv_bfloat16 g_bh[2592 * 64];
__device__ __align__(16) __nv_bfloat16 g_bl[2592 * 64];

// ---------------- PTX helpers ----------------------------------------------
DINL uint32_t smem_u32(const void* p) {
    uint32_t a;
    asm("{ .reg .u64 t; cvta.to.shared.u64 t, %1; cvt.u32.u64 %0, t; }" : "=r"(a) : "l"(p));
    return a;
}
DINL void cp16(uint32_t s, const void* g) {
    asm volatile("cp.async.cg.shared.global [%0], [%1], 16;" :: "r"(s), "l"(g));
}
DINL void cp_commit() { asm volatile("cp.async.commit_group;"); }
DINL void cp_wait2()  { asm volatile("cp.async.wait_group 2;" ::: "memory"); }
DINL void cp_wait1()  { asm volatile("cp.async.wait_group 1;" ::: "memory"); }
DINL void cp_wait0()  { asm volatile("cp.async.wait_group 0;" ::: "memory"); }

DINL void ldm4(uint32_t& r0, uint32_t& r1, uint32_t& r2, uint32_t& r3, uint32_t a) {
    asm volatile("ldmatrix.sync.aligned.m8n8.x4.shared.b16 {%0,%1,%2,%3}, [%4];"
                 : "=r"(r0), "=r"(r1), "=r"(r2), "=r"(r3) : "r"(a));
}
DINL void mma16816(float& d0, float& d1, float& d2, float& d3,
                   uint32_t a0, uint32_t a1, uint32_t a2, uint32_t a3,
                   uint32_t b0, uint32_t b1) {
    asm volatile(
        "mma.sync.aligned.m16n8k16.row.col.f32.bf16.bf16.f32 "
        "{%0,%1,%2,%3}, {%4,%5,%6,%7}, {%8,%9}, {%0,%1,%2,%3};"
        : "+f"(d0), "+f"(d1), "+f"(d2), "+f"(d3)
        : "r"(a0), "r"(a1), "r"(a2), "r"(a3), "r"(b0), "r"(b1));
}

// ---------------- prep 1: x -> channel-last bf16 hi/lo ----------------------
__global__ void prep_x(const float* __restrict__ x) {
    __shared__ float t[144 * 33];
    int bid = blockIdx.x;                 // 8192 = 8b*32x*32y
    int b = bid >> 10, xx = (bid >> 5) & 31, y = bid & 31;
    for (int i = threadIdx.x; i < 144 * 32; i += 128) {
        int ci = i >> 5, z = i & 31;
        t[ci * 33 + z] = x[(size_t)(b * 144 + ci) * 32768 + xx * 1024 + y * 32 + z];
    }
    __syncthreads();
    size_t rb = ((((size_t)b * 32 + xx) * 32 + y) * 32) * 72;   // uint32 units
    uint32_t* oh = (uint32_t*)g_xh;
    uint32_t* ol = (uint32_t*)g_xl;
    for (int j = threadIdx.x; j < 32 * 72; j += 128) {
        int z = j / 72, cp = j % 72, ci = cp * 2;
        float f0 = t[ci * 33 + z], f1 = t[(ci + 1) * 33 + z];
        __nv_bfloat16 h0 = __float2bfloat16(f0), h1 = __float2bfloat16(f1);
        __nv_bfloat16 l0 = __float2bfloat16(f0 - __bfloat162float(h0));
        __nv_bfloat16 l1 = __float2bfloat16(f1 - __bfloat162float(h1));
        __nv_bfloat162 vh; vh.x = h0; vh.y = h1;
        __nv_bfloat162 vl; vl.x = l0; vl.y = l1;
        oh[rb + (size_t)z * 72 + cp] = *(uint32_t*)&vh;
        ol[rb + (size_t)z * 72 + cp] = *(uint32_t*)&vl;
    }
}

// ---------------- prep 2: W -> B rows hi/lo ---------------------------------
__global__ void prep_w(const float* __restrict__ W) {
    int i = blockIdx.x * 256 + threadIdx.x;
    if (i >= 2592 * 64) return;
    int row = i >> 6, cil = i & 63;
    int co = row & 31, tt = row >> 5;
    int ky = tt % 3, chunk = (tt / 3) % 3, kxkz = tt / 9;
    int kx = kxkz / 3, kz = kxkz % 3;
    int ci = chunk * 64 + cil;
    float f = (ci < 144) ? W[(size_t)(co * 144 + ci) * 27 + kx * 9 + ky * 3 + kz] : 0.f;
    __nv_bfloat16 h = __float2bfloat16(f);
    g_bh[i] = h;
    g_bl[i] = __float2bfloat16(f - __bfloat162float(h));
}

// ---------------- main: implicit GEMM, M=256, pipelined fragments -----------
static constexpr int A_SLOT = 328 * 128;           // 41984
static constexpr int A_BUF  = 2 * A_SLOT;          // 83968
static constexpr int OFF_B  = 2 * A_BUF;           // 167936
static constexpr int B_SLOT = 96 * 128;            // 12288
static constexpr int B_BUF  = 2 * B_SLOT;          // 24576
static constexpr int SMEM_TOT = OFF_B + 2 * B_BUF; // 217088

DINL void stage_A(int u, int b, int ox, int oy0, int tid, uint32_t dst) {
    int kx = u / 3, chunk = u % 3;
    int cgmax = (chunk < 2) ? 8 : 2;
    int cgsh  = (chunk < 2) ? 3 : 1;
    int f0 = ((b * 32 + ox + kx) * 32 + oy0) * 32;
    const char* gh = (const char*)g_xh + (size_t)f0 * 288 + chunk * 128;
    const char* gl = (const char*)g_xl + (size_t)f0 * 288 + chunk * 128;
    for (int idx = tid; idx < 328 * cgmax; idx += 256) {
        int row = idx >> cgsh, cg = idx & (cgmax - 1);
        uint32_t d = dst + row * 128 + ((cg ^ (row & 7)) << 4);
        cp16(d,          gh + (size_t)row * 288 + cg * 16);
        cp16(d + A_SLOT, gl + (size_t)row * 288 + cg * 16);
    }
}
DINL void stage_B(int s, int tid, uint32_t dst) {
    int kx = s / 9, chunk = (s % 9) / 3, kz = s % 3;
    int cgmax = (chunk < 2) ? 8 : 2;
    int cgsh  = (chunk < 2) ? 3 : 1;
    int brow0 = ((kx * 3 + kz) * 9 + chunk * 3) * 32;
    const char* gh = (const char*)g_bh + (size_t)brow0 * 128;
    const char* gl = (const char*)g_bl + (size_t)brow0 * 128;
    for (int idx = tid; idx < 96 * cgmax; idx += 256) {
        int row = idx >> cgsh, cg = idx & (cgmax - 1);
        uint32_t d = dst + row * 128 + ((cg ^ (row & 7)) << 4);
        cp16(d,          gh + (size_t)row * 128 + cg * 16);
        cp16(d + B_SLOT, gl + (size_t)row * 128 + cg * 16);
    }
}

// register fragment set for one (ks,ky) iteration
struct Frags {
    uint32_t bh[8], bl[8];      // B hi/lo: 4 n-tiles x (r0..r3 order)
    uint32_t a[2][4], q[2][4];  // A hi/lo per m-tile
};

DINL void frag_load(Frags& f, uint32_t abuf, uint32_t bbuf, int ks, int ky,
                    int kz, int w, int lrow, int lblk, uint32_t csA, uint32_t csB) {
    uint32_t colA = (uint32_t)(((ks * 2 + lblk) ^ (int)csA) << 4);
    uint32_t colB = (uint32_t)(((ks * 2 + lblk) ^ (int)csB) << 4);
    uint32_t br0 = (uint32_t)(ky * 32 + lrow) * 128;
    uint32_t br1 = (uint32_t)(ky * 32 + 16 + lrow) * 128;
    ldm4(f.bh[0], f.bh[1], f.bh[2], f.bh[3], bbuf + br0 + colB);
    ldm4(f.bh[4], f.bh[5], f.bh[6], f.bh[7], bbuf + br1 + colB);
    ldm4(f.bl[0], f.bl[1], f.bl[2], f.bl[3], bbuf + B_SLOT + br0 + colB);
    ldm4(f.bl[4], f.bl[5], f.bl[6], f.bl[7], bbuf + B_SLOT + br1 + colB);
#pragma unroll
    for (int m = 0; m < 2; m++) {
        uint32_t arow = (uint32_t)(w * 32 + m * 16 + ky * 32 + kz + lrow) * 128;
        ldm4(f.a[m][0], f.a[m][1], f.a[m][2], f.a[m][3], abuf + arow + colA);
        ldm4(f.q[m][0], f.q[m][1], f.q[m][2], f.q[m][3], abuf + A_SLOT + arow + colA);
    }
}

DINL void frag_mma(float (&c)[2][4][4], const Frags& f) {
#pragma unroll
    for (int m = 0; m < 2; m++) {
        // pass hh
        mma16816(c[m][0][0], c[m][0][1], c[m][0][2], c[m][0][3], f.a[m][0], f.a[m][1], f.a[m][2], f.a[m][3], f.bh[0], f.bh[2]);
        mma16816(c[m][1][0], c[m][1][1], c[m][1][2], c[m][1][3], f.a[m][0], f.a[m][1], f.a[m][2], f.a[m][3], f.bh[1], f.bh[3]);
        mma16816(c[m][2][0], c[m][2][1], c[m][2][2], c[m][2][3], f.a[m][0], f.a[m][1], f.a[m][2], f.a[m][3], f.bh[4], f.bh[6]);
        mma16816(c[m][3][0], c[m][3][1], c[m][3][2], c[m][3][3], f.a[m][0], f.a[m][1], f.a[m][2], f.a[m][3], f.bh[5], f.bh[7]);
        // pass hl
        mma16816(c[m][0][0], c[m][0][1], c[m][0][2], c[m][0][3], f.a[m][0], f.a[m][1], f.a[m][2], f.a[m][3], f.bl[0], f.bl[2]);
        mma16816(c[m][1][0], c[m][1][1], c[m][1][2], c[m][1][3], f.a[m][0], f.a[m][1], f.a[m][2], f.a[m][3], f.bl[1], f.bl[3]);
        mma16816(c[m][2][0], c[m][2][1], c[m][2][2], c[m][2][3], f.a[m][0], f.a[m][1], f.a[m][2], f.a[m][3], f.bl[4], f.bl[6]);
        mma16816(c[m][3][0], c[m][3][1], c[m][3][2], c[m][3][3], f.a[m][0], f.a[m][1], f.a[m][2], f.a[m][3], f.bl[5], f.bl[7]);
        // pass lh
        mma16816(c[m][0][0], c[m][0][1], c[m][0][2], c[m][0][3], f.q[m][0], f.q[m][1], f.q[m][2], f.q[m][3], f.bh[0], f.bh[2]);
        mma16816(c[m][1][0], c[m][1][1], c[m][1][2], c[m][1][3], f.q[m][0], f.q[m][1], f.q[m][2], f.q[m][3], f.bh[1], f.bh[3]);
        mma16816(c[m][2][0], c[m][2][1], c[m][2][2], c[m][2][3], f.q[m][0], f.q[m][1], f.q[m][2], f.q[m][3], f.bh[4], f.bh[6]);
        mma16816(c[m][3][0], c[m][3][1], c[m][3][2], c[m][3][3], f.q[m][0], f.q[m][1], f.q[m][2], f.q[m][3], f.bh[5], f.bh[7]);
    }
}

// Fully-unrolled pipelined unit: loads for t+1 issue before MMAs of t.
template <int KSTEPS>
DINL void run_unit(float (&c)[2][4][4], uint32_t abuf, uint32_t bbuf,
                   int kz, int w, int lrow, int lblk, uint32_t csA, uint32_t csB) {
    constexpr int ITERS = KSTEPS * 3;
    Frags fr[2];
    frag_load(fr[0], abuf, bbuf, 0, 0, kz, w, lrow, lblk, csA, csB);
#pragma unroll
    for (int t = 0; t < ITERS; t++) {
        if (t + 1 < ITERS)
            frag_load(fr[(t + 1) & 1], abuf, bbuf, (t + 1) / 3, (t + 1) % 3,
                      kz, w, lrow, lblk, csA, csB);
        frag_mma(c, fr[t & 1]);
    }
}

__global__ __launch_bounds__(256, 1)
void conv_mma(float* __restrict__ out) {
    extern __shared__ char smem[];
    uint32_t sb = smem_u32(smem);
    int tid = threadIdx.x, w = tid >> 5, lane = tid & 31;

    int bid = blockIdx.x;                       // 960 = 8b * 30ox * 4oyblk
    int b = bid / 120, r = bid % 120, ox = r / 4, oy0 = (r % 4) * 8;

    int lrow = (lane & 7) + (((lane >> 3) & 1) << 3);
    int lblk = lane >> 4;

    float c[2][4][4];
#pragma unroll
    for (int m = 0; m < 2; m++)
#pragma unroll
        for (int n = 0; n < 4; n++)
#pragma unroll
            for (int j = 0; j < 4; j++) c[m][n][j] = 0.f;

    stage_A(0, b, ox, oy0, tid, sb);
    cp_commit();
    stage_B(0, tid, sb + OFF_B);
    cp_commit();

    for (int s = 0; s < 27; s++) {
        int u = s / 3, kz = s % 3, chunk = u % 3;
        uint32_t abuf = sb + (u & 1) * A_BUF;
        uint32_t bbuf = sb + OFF_B + (s & 1) * B_BUF;

        __syncthreads();
        int n_new = 0;
        if (kz == 0 && u + 1 < 9) {
            stage_A(u + 1, b, ox, oy0, tid, sb + ((u + 1) & 1) * A_BUF);
            cp_commit(); n_new++;
        }
        if (s + 1 < 27) {
            stage_B(s + 1, tid, sb + OFF_B + ((s + 1) & 1) * B_BUF);
            cp_commit(); n_new++;
        }
        if (n_new == 2) cp_wait2(); else if (n_new == 1) cp_wait1(); else cp_wait0();
        __syncthreads();

        uint32_t csA = (uint32_t)((lane + kz) & 7);
        uint32_t csB = (uint32_t)(lane & 7);
        if (chunk < 2) run_unit<4>(c, abuf, bbuf, kz, w, lrow, lblk, csA, csB);
        else           run_unit<1>(c, abuf, bbuf, kz, w, lrow, lblk, csA, csB);
    }

    // ---- epilogue ----
    int rr = lane >> 2;
    int nb = (lane & 3) * 2;
#pragma unroll
    for (int m = 0; m < 2; m++)
#pragma unroll
        for (int half = 0; half < 2; half++) {
            int Mrow = w * 32 + m * 16 + rr + half * 8;
            int oy = oy0 + (Mrow >> 5);
            int oz = Mrow & 31;
            if (oy < 30 && oz < 30) {
                float* ob = out + (size_t)b * 32 * 27000 + ox * 900 + oy * 30 + oz;
#pragma unroll
                for (int nt = 0; nt < 4; nt++) {
                    int n = nt * 8 + nb;
                    ob[(size_t)n * 27000]       = c[m][nt][half * 2];
                    ob[(size_t)(n + 1) * 27000] = c[m][nt][half * 2 + 1];
                }
            }
        }
}

// ---------------- host ------------------------------------------------------
extern "C" void kernel_launch(void* const* d_in, const int* in_sizes, int n_in,
                              void* d_out, int out_size) {
    const float* x = (const float*)d_in[0];
    const float* W = (const float*)d_in[1];
    if (n_in >= 2 && in_sizes[0] == 124416) { const float* t = x; x = W; W = t; }
    float* out = (float*)d_out;

    cudaFuncSetAttribute(conv_mma, cudaFuncAttributeMaxDynamicSharedMemorySize, SMEM_TOT);

    prep_x<<<8192, 128>>>(x);
    prep_w<<<(2592 * 64 + 255) / 256, 256>>>(W);
    conv_mma<<<960, 256, SMEM_TOT>>>(out);
}

// round 16
// speedup vs baseline: 2.4271x; 2.3033x over previous
// R16: single-pass fp16 (3x fewer MACs than split-bf16; err model predicts ~4e-4).
// R13 tiling: M=256, 8 warps, A+B double-buffered; smem 106KB -> occupancy 2.
#include <cuda_runtime.h>
#include <cuda_fp16.h>
#include <cstdint>

#define DINL __device__ __forceinline__

// ---------------- device scratch (no allocations allowed) -------------------
// x channel-last fp16: row = flat(b,x,y,z), 144 ci per row (288B).
// +1024 pad rows for window-shift overhang (lands in discarded outputs).
__device__ __align__(16) __half g_xh[(262144 + 1024) * 144];
// W rows: [(kx*3+kz)*9 + chunk*3 + ky][co32][ci64] = 2592 rows x 128B
__device__ __align__(16) __half g_bh[2592 * 64];

// ---------------- PTX helpers ----------------------------------------------
DINL uint32_t smem_u32(const void* p) {
    uint32_t a;
    asm("{ .reg .u64 t; cvta.to.shared.u64 t, %1; cvt.u32.u64 %0, t; }" : "=r"(a) : "l"(p));
    return a;
}
DINL void cp16(uint32_t s, const void* g) {
    asm volatile("cp.async.cg.shared.global [%0], [%1], 16;" :: "r"(s), "l"(g));
}
DINL void cp_commit() { asm volatile("cp.async.commit_group;"); }
DINL void cp_wait2()  { asm volatile("cp.async.wait_group 2;" ::: "memory"); }
DINL void cp_wait1()  { asm volatile("cp.async.wait_group 1;" ::: "memory"); }
DINL void cp_wait0()  { asm volatile("cp.async.wait_group 0;" ::: "memory"); }

DINL void ldm4(uint32_t& r0, uint32_t& r1, uint32_t& r2, uint32_t& r3, uint32_t a) {
    asm volatile("ldmatrix.sync.aligned.m8n8.x4.shared.b16 {%0,%1,%2,%3}, [%4];"
                 : "=r"(r0), "=r"(r1), "=r"(r2), "=r"(r3) : "r"(a));
}
DINL void mma16816(float& d0, float& d1, float& d2, float& d3,
                   uint32_t a0, uint32_t a1, uint32_t a2, uint32_t a3,
                   uint32_t b0, uint32_t b1) {
    asm volatile(
        "mma.sync.aligned.m16n8k16.row.col.f32.f16.f16.f32 "
        "{%0,%1,%2,%3}, {%4,%5,%6,%7}, {%8,%9}, {%0,%1,%2,%3};"
        : "+f"(d0), "+f"(d1), "+f"(d2), "+f"(d3)
        : "r"(a0), "r"(a1), "r"(a2), "r"(a3), "r"(b0), "r"(b1));
}

// ---------------- prep 1: x -> channel-last fp16 ----------------------------
__global__ void prep_x(const float* __restrict__ x) {
    __shared__ float t[144 * 33];
    int bid = blockIdx.x;                 // 8192 = 8b*32x*32y
    int b = bid >> 10, xx = (bid >> 5) & 31, y = bid & 31;
    for (int i = threadIdx.x; i < 144 * 32; i += 128) {
        int ci = i >> 5, z = i & 31;
        t[ci * 33 + z] = x[(size_t)(b * 144 + ci) * 32768 + xx * 1024 + y * 32 + z];
    }
    __syncthreads();
    size_t rb = ((((size_t)b * 32 + xx) * 32 + y) * 32) * 72;   // uint32 units
    uint32_t* oh = (uint32_t*)g_xh;
    for (int j = threadIdx.x; j < 32 * 72; j += 128) {
        int z = j / 72, cp = j % 72, ci = cp * 2;
        __half2 vh;
        vh.x = __float2half(t[ci * 33 + z]);
        vh.y = __float2half(t[(ci + 1) * 33 + z]);
        oh[rb + (size_t)z * 72 + cp] = *(uint32_t*)&vh;
    }
}

// ---------------- prep 2: W -> B rows fp16 ----------------------------------
__global__ void prep_w(const float* __restrict__ W) {
    int i = blockIdx.x * 256 + threadIdx.x;
    if (i >= 2592 * 64) return;
    int row = i >> 6, cil = i & 63;
    int co = row & 31, tt = row >> 5;
    int ky = tt % 3, chunk = (tt / 3) % 3, kxkz = tt / 9;
    int kx = kxkz / 3, kz = kxkz % 3;
    int ci = chunk * 64 + cil;
    float f = (ci < 144) ? W[(size_t)(co * 144 + ci) * 27 + kx * 9 + ky * 3 + kz] : 0.f;
    g_bh[i] = __float2half(f);
}

// ---------------- main: implicit GEMM, M=256, fp16 single-pass ---------------
// CTA: M=256 = 8oy x 32oz, N=32. 256 thr, 8 warps; warp w owns M [w*32,w*32+32).
// Grid 960 = 8b * 30ox * 4oyblk.
// A unit (kx,chunk): 328-row slab (row = flat(y_local,z)); kz & ky = row offsets
// at read time; A swizzle term (lane+kz)&7. B unit (kx,chunk,kz): 96 rows.
// smem: A 2 x 41984 = 83968 | B 2 x 12288 = 24576 -> 108544 (106KB), occ 2.
static constexpr int A_SLOT = 328 * 128;            // 41984
static constexpr int OFF_B  = 2 * A_SLOT;           // 83968
static constexpr int B_SLOT = 96 * 128;             // 12288
static constexpr int SMEM_TOT = OFF_B + 2 * B_SLOT; // 108544

DINL void stage_A(int u, int b, int ox, int oy0, int tid, uint32_t dst) {
    int kx = u / 3, chunk = u % 3;
    int cgmax = (chunk < 2) ? 8 : 2;
    int cgsh  = (chunk < 2) ? 3 : 1;
    int f0 = ((b * 32 + ox + kx) * 32 + oy0) * 32;
    const char* gh = (const char*)g_xh + (size_t)f0 * 288 + chunk * 128;
    for (int idx = tid; idx < 328 * cgmax; idx += 256) {
        int row = idx >> cgsh, cg = idx & (cgmax - 1);
        cp16(dst + row * 128 + ((cg ^ (row & 7)) << 4),
             gh + (size_t)row * 288 + cg * 16);
    }
}
DINL void stage_B(int s, int tid, uint32_t dst) {
    int kx = s / 9, chunk = (s % 9) / 3, kz = s % 3;
    int cgmax = (chunk < 2) ? 8 : 2;
    int cgsh  = (chunk < 2) ? 3 : 1;
    int brow0 = ((kx * 3 + kz) * 9 + chunk * 3) * 32;
    const char* gh = (const char*)g_bh + (size_t)brow0 * 128;
    for (int idx = tid; idx < 96 * cgmax; idx += 256) {
        int row = idx >> cgsh, cg = idx & (cgmax - 1);
        cp16(dst + row * 128 + ((cg ^ (row & 7)) << 4),
             gh + (size_t)row * 128 + cg * 16);
    }
}

__global__ __launch_bounds__(256, 2)
void conv_mma(float* __restrict__ out) {
    extern __shared__ char smem[];
    uint32_t sb = smem_u32(smem);
    int tid = threadIdx.x, w = tid >> 5, lane = tid & 31;

    int bid = blockIdx.x;                       // 960 = 8b * 30ox * 4oyblk
    int b = bid / 120, r = bid % 120, ox = r / 4, oy0 = (r % 4) * 8;

    // canonical ldmatrix.x4 lane geometry (proven R11/R13)
    int lrow = (lane & 7) + (((lane >> 3) & 1) << 3);
    int lblk = lane >> 4;

    float c[2][4][4];
#pragma unroll
    for (int m = 0; m < 2; m++)
#pragma unroll
        for (int n = 0; n < 4; n++)
#pragma unroll
            for (int j = 0; j < 4; j++) c[m][n][j] = 0.f;

    stage_A(0, b, ox, oy0, tid, sb);
    cp_commit();
    stage_B(0, tid, sb + OFF_B);
    cp_commit();

    for (int s = 0; s < 27; s++) {
        int u = s / 3, kz = s % 3, chunk = u % 3;
        uint32_t abuf = sb + (u & 1) * A_SLOT;
        uint32_t bbuf = sb + OFF_B + (s & 1) * B_SLOT;

        __syncthreads();
        int n_new = 0;
        if (kz == 0 && u + 1 < 9) {
            stage_A(u + 1, b, ox, oy0, tid, sb + ((u + 1) & 1) * A_SLOT);
            cp_commit(); n_new++;
        }
        if (s + 1 < 27) {
            stage_B(s + 1, tid, sb + OFF_B + ((s + 1) & 1) * B_SLOT);
            cp_commit(); n_new++;
        }
        if (n_new == 2) cp_wait2(); else if (n_new == 1) cp_wait1(); else cp_wait0();
        __syncthreads();

        int ksteps = (chunk < 2) ? 4 : 1;
        uint32_t csA = (uint32_t)((lane + kz) & 7);
        uint32_t csB = (uint32_t)(lane & 7);
#pragma unroll 1
        for (int ks = 0; ks < ksteps; ks++) {
            uint32_t colA = (uint32_t)(((ks * 2 + lblk) ^ csA) << 4);
            uint32_t colB = (uint32_t)(((ks * 2 + lblk) ^ csB) << 4);
#pragma unroll
            for (int ky = 0; ky < 3; ky++) {
                uint32_t br0 = (uint32_t)(ky * 32 + lrow) * 128;
                uint32_t br1 = (uint32_t)(ky * 32 + 16 + lrow) * 128;
                uint32_t bh0, bh1, bh2, bh3, bh4, bh5, bh6, bh7;
                ldm4(bh0, bh1, bh2, bh3, bbuf + br0 + colB);  // nt0=(bh0,bh2) nt1=(bh1,bh3)
                ldm4(bh4, bh5, bh6, bh7, bbuf + br1 + colB);  // nt2=(bh4,bh6) nt3=(bh5,bh7)
#pragma unroll
                for (int m = 0; m < 2; m++) {
                    uint32_t arow =
                        (uint32_t)(w * 32 + m * 16 + ky * 32 + kz + lrow) * 128;
                    uint32_t a0, a1, a2, a3;
                    ldm4(a0, a1, a2, a3, abuf + arow + colA);
                    mma16816(c[m][0][0], c[m][0][1], c[m][0][2], c[m][0][3], a0, a1, a2, a3, bh0, bh2);
                    mma16816(c[m][1][0], c[m][1][1], c[m][1][2], c[m][1][3], a0, a1, a2, a3, bh1, bh3);
                    mma16816(c[m][2][0], c[m][2][1], c[m][2][2], c[m][2][3], a0, a1, a2, a3, bh4, bh6);
                    mma16816(c[m][3][0], c[m][3][1], c[m][3][2], c[m][3][3], a0, a1, a2, a3, bh5, bh7);
                }
            }
        }
    }

    // ---- epilogue: Mrow = w*32 + m*16 + rr(+8); oy = oy0 + Mrow/32, oz = Mrow%32
    int rr = lane >> 2;
    int nb = (lane & 3) * 2;
#pragma unroll
    for (int m = 0; m < 2; m++)
#pragma unroll
        for (int half = 0; half < 2; half++) {
            int Mrow = w * 32 + m * 16 + rr + half * 8;
            int oy = oy0 + (Mrow >> 5);
            int oz = Mrow & 31;
            if (oy < 30 && oz < 30) {
                float* ob = out + (size_t)b * 32 * 27000 + ox * 900 + oy * 30 + oz;
#pragma unroll
                for (int nt = 0; nt < 4; nt++) {
                    int n = nt * 8 + nb;
                    ob[(size_t)n * 27000]       = c[m][nt][half * 2];
                    ob[(size_t)(n + 1) * 27000] = c[m][nt][half * 2 + 1];
                }
            }
        }
}

// ---------------- host ------------------------------------------------------
extern "C" void kernel_launch(void* const* d_in, const int* in_sizes, int n_in,
                              void* d_out, int out_size) {
    const float* x = (const float*)d_in[0];
    const float* W = (const float*)d_in[1];
    if (n_in >= 2 && in_sizes[0] == 124416) { const float* t = x; x = W; W = t; }
    float* out = (float*)d_out;

    cudaFuncSetAttribute(conv_mma, cudaFuncAttributeMaxDynamicSharedMemorySize, SMEM_TOT);

    prep_x<<<8192, 128>>>(x);
    prep_w<<<(2592 * 64 + 255) / 256, 256>>>(W);
    conv_mma<<<960, 256, SMEM_TOT>>>(out);
}